// round 1
// baseline (speedup 1.0000x reference)
#include <cuda_runtime.h>
#include <cuda_bf16.h>
#include <math.h>

#define T_LEN 4096
#define DIM 768
#define HEADS 12
#define HD 64
#define RMS_EPS 1.1920928955078125e-07f
#define ATTN_SCALE 0.12f

// ---------------- scratch (no allocations allowed) ----------------
__device__ float g_qkv[T_LEN * 3 * DIM];            // [T][3*768]
__device__ float g_Q[HEADS * T_LEN * HD];           // [h][t][d]
__device__ float g_K[HEADS * T_LEN * HD];
__device__ float g_V[HEADS * T_LEN * HD];
__device__ float g_Y[T_LEN * DIM];                  // attention out [t][h*64+d]

// ---------------- GEMM: C[M,N] = A[M,K] * B[N,K]^T (both K-contiguous) ----------------
// 128x128 tile, BK=16, 256 threads, 8x8 per thread.
__global__ __launch_bounds__(256) void gemm_nt(const float* __restrict__ A,
                                               const float* __restrict__ B,
                                               float* __restrict__ C,
                                               int M, int N, int K) {
    __shared__ float As[16][128];
    __shared__ float Bs[16][128];
    const int tid = threadIdx.x;
    const int tx = tid & 15;        // col group
    const int ty = tid >> 4;        // row group
    const int row0 = blockIdx.y * 128;
    const int col0 = blockIdx.x * 128;

    float acc[8][8];
#pragma unroll
    for (int i = 0; i < 8; i++)
#pragma unroll
        for (int j = 0; j < 8; j++) acc[i][j] = 0.f;

    for (int k0 = 0; k0 < K; k0 += 16) {
#pragma unroll
        for (int i = 0; i < 2; i++) {
            int id = tid + i * 256;          // 0..511 float4 slots
            int r = id >> 2;                 // 0..127
            int c = (id & 3) << 2;           // 0,4,8,12
            float4 a = *(const float4*)&A[(size_t)(row0 + r) * K + k0 + c];
            As[c + 0][r] = a.x; As[c + 1][r] = a.y;
            As[c + 2][r] = a.z; As[c + 3][r] = a.w;
            float4 b = *(const float4*)&B[(size_t)(col0 + r) * K + k0 + c];
            Bs[c + 0][r] = b.x; Bs[c + 1][r] = b.y;
            Bs[c + 2][r] = b.z; Bs[c + 3][r] = b.w;
        }
        __syncthreads();
#pragma unroll
        for (int k = 0; k < 16; k++) {
            float a[8], b[8];
            *(float4*)&a[0] = *(float4*)&As[k][ty * 8];
            *(float4*)&a[4] = *(float4*)&As[k][ty * 8 + 4];
            *(float4*)&b[0] = *(float4*)&Bs[k][tx * 8];
            *(float4*)&b[4] = *(float4*)&Bs[k][tx * 8 + 4];
#pragma unroll
            for (int i = 0; i < 8; i++)
#pragma unroll
                for (int j = 0; j < 8; j++) acc[i][j] = fmaf(a[i], b[j], acc[i][j]);
        }
        __syncthreads();
    }

#pragma unroll
    for (int i = 0; i < 8; i++) {
        float* cp = &C[(size_t)(row0 + ty * 8 + i) * N + col0 + tx * 8];
        float4 v0 = make_float4(acc[i][0], acc[i][1], acc[i][2], acc[i][3]);
        float4 v1 = make_float4(acc[i][4], acc[i][5], acc[i][6], acc[i][7]);
        *(float4*)&cp[0] = v0;
        *(float4*)&cp[4] = v1;
    }
}

// ---------------- prep: RMS norm + rotary + relayout to [h][t][d] ----------------
// one warp per (t, h) pair; lane l owns elements l and l+32 of the 64-dim head.
__global__ void prep_kernel(const float* __restrict__ qkv,
                            float* __restrict__ Q, float* __restrict__ K,
                            float* __restrict__ V) {
    int gwarp = (blockIdx.x * blockDim.x + threadIdx.x) >> 5;
    int lane = threadIdx.x & 31;
    if (gwarp >= T_LEN * HEADS) return;
    int t = gwarp / HEADS;
    int h = gwarp % HEADS;
    const float* base = qkv + (size_t)t * (3 * DIM) + h * HD;

    float q1 = base[lane],            q2 = base[lane + 32];
    float k1 = base[DIM + lane],      k2 = base[DIM + lane + 32];
    float v1 = base[2 * DIM + lane],  v2 = base[2 * DIM + lane + 32];

    float sq = q1 * q1 + q2 * q2;
    float sk = k1 * k1 + k2 * k2;
#pragma unroll
    for (int o = 16; o > 0; o >>= 1) {
        sq += __shfl_xor_sync(0xffffffffu, sq, o);
        sk += __shfl_xor_sync(0xffffffffu, sk, o);
    }
    float rq = rsqrtf(sq * (1.f / 64.f) + RMS_EPS);
    float rk = rsqrtf(sk * (1.f / 64.f) + RMS_EPS);
    q1 *= rq; q2 *= rq;
    k1 *= rk; k2 *= rk;

    // rotary: freqs[j] = (1/1024)^(j/15) for j<16, else 0.  1/1024 = 2^-10 exactly.
    float freq = (lane < 16) ? exp2f((float)lane * (-10.0f / 15.0f)) : 0.0f;
    float theta = (float)t * freq;     // same fp32 product as the reference
    float s, c;
    sincosf(theta, &s, &c);

    float qy1 = q1 * c + q2 * s;
    float qy2 = -q1 * s + q2 * c;
    float ky1 = k1 * c + k2 * s;
    float ky2 = -k1 * s + k2 * c;

    size_t o = ((size_t)h * T_LEN + t) * HD;
    Q[o + lane] = qy1;  Q[o + lane + 32] = qy2;
    K[o + lane] = ky1;  K[o + lane + 32] = ky2;
    V[o + lane] = v1;   V[o + lane + 32] = v2;
}

// ---------------- causal flash attention, fp32, 1 query row per thread ----------------
// block: 128 threads = 128 query rows; loop over key tiles of 32 in smem.
__global__ __launch_bounds__(128, 2)
void flash_attn(const float* __restrict__ Q, const float* __restrict__ K,
                const float* __restrict__ V, float* __restrict__ Y) {
    __shared__ float Ks[32][HD];
    __shared__ float Vs[32][HD];
    const int h = blockIdx.y;
    const int qb = (gridDim.x - 1) - blockIdx.x;   // heaviest blocks launch first
    const int tid = threadIdx.x;
    const int q = qb * 128 + tid;

    float qr[HD];
    const float4* Qp = (const float4*)(Q + ((size_t)h * T_LEN + q) * HD);
#pragma unroll
    for (int i = 0; i < 16; i++) {
        float4 v4 = Qp[i];
        qr[4 * i + 0] = v4.x; qr[4 * i + 1] = v4.y;
        qr[4 * i + 2] = v4.z; qr[4 * i + 3] = v4.w;
    }

    float acc[HD];
#pragma unroll
    for (int d = 0; d < HD; d++) acc[d] = 0.f;
    float m = -1e30f, l = 0.f;

    const int nk = qb * 128 + 128;     // keys covered (mask handles per-thread diag)
    const float* Kh = K + (size_t)h * T_LEN * HD;
    const float* Vh = V + (size_t)h * T_LEN * HD;

    for (int k0 = 0; k0 < nk; k0 += 32) {
        __syncthreads();
        const float4* Kp = (const float4*)(Kh + (size_t)k0 * HD);
        const float4* Vp = (const float4*)(Vh + (size_t)k0 * HD);
#pragma unroll
        for (int i = 0; i < 4; i++) {
            int idx = tid + i * 128;   // 0..511 float4 slots of 32x64 tile
            int r = idx >> 4, c = (idx & 15) << 2;
            *(float4*)&Ks[r][c] = Kp[idx];
            *(float4*)&Vs[r][c] = Vp[idx];
        }
        __syncthreads();

        float s[32];
#pragma unroll
        for (int j = 0; j < 32; j++) {
            float sj = 0.f;
#pragma unroll
            for (int d = 0; d < HD; d++) sj = fmaf(qr[d], Ks[j][d], sj);
            s[j] = (k0 + j <= q) ? sj * ATTN_SCALE : -1e30f;
        }
        float tm = m;
#pragma unroll
        for (int j = 0; j < 32; j++) tm = fmaxf(tm, s[j]);
        float scale = __expf(m - tm);
        m = tm;
        l *= scale;
#pragma unroll
        for (int d = 0; d < HD; d++) acc[d] *= scale;
#pragma unroll
        for (int j = 0; j < 32; j++) {
            float p = __expf(s[j] - m);
            l += p;
#pragma unroll
            for (int d = 0; d < HD; d++) acc[d] = fmaf(p, Vs[j][d], acc[d]);
        }
    }

    float inv = 1.f / l;
    float* Yp = Y + (size_t)q * DIM + h * HD;
#pragma unroll
    for (int i = 0; i < 16; i++) {
        float4 v4 = make_float4(acc[4 * i] * inv, acc[4 * i + 1] * inv,
                                acc[4 * i + 2] * inv, acc[4 * i + 3] * inv);
        *(float4*)&Yp[4 * i] = v4;
    }
}

// ---------------- launch ----------------
extern "C" void kernel_launch(void* const* d_in, const int* in_sizes, int n_in,
                              void* d_out, int out_size) {
    const float* x = (const float*)d_in[0];        // [1,4096,768]
    const float* qkv_w = (const float*)d_in[1];    // [3,768,768]
    const float* c_proj_w = (const float*)d_in[2]; // [768,768]
    float* out = (float*)d_out;                    // [1,4096,768]

    float *qkv, *Qb, *Kb, *Vb, *Yb;
    cudaGetSymbolAddress((void**)&qkv, g_qkv);
    cudaGetSymbolAddress((void**)&Qb, g_Q);
    cudaGetSymbolAddress((void**)&Kb, g_K);
    cudaGetSymbolAddress((void**)&Vb, g_V);
    cudaGetSymbolAddress((void**)&Yb, g_Y);

    // 1) qkv = x @ qkv_w^T   (N = 3*768 = 2304)
    {
        dim3 grid(2304 / 128, T_LEN / 128);
        gemm_nt<<<grid, 256>>>(x, qkv_w, qkv, T_LEN, 2304, DIM);
    }
    // 2) RMS + rotary + relayout
    {
        int warps = T_LEN * HEADS;                 // 49152
        int threads = 256;
        int blocks = (warps * 32 + threads - 1) / threads;
        prep_kernel<<<blocks, threads>>>(qkv, Qb, Kb, Vb);
    }
    // 3) causal flash attention
    {
        dim3 grid(T_LEN / 128, HEADS);
        flash_attn<<<grid, 128>>>(Qb, Kb, Vb, Yb);
    }
    // 4) out = Y @ c_proj_w^T
    {
        dim3 grid(DIM / 128, T_LEN / 128);
        gemm_nt<<<grid, 256>>>(Yb, c_proj_w, out, T_LEN, DIM, DIM);
    }
}

// round 2
// speedup vs baseline: 1.2692x; 1.2692x over previous
#include <cuda_runtime.h>
#include <cuda_bf16.h>
#include <math.h>

#define T_LEN 4096
#define DIM 768
#define HEADS 12
#define HD 64
#define RMS_EPS 1.1920928955078125e-07f
#define ATTN_SCALE 0.12f
#define BM 64
#define BN 64
#define SPAD 68   // smem row stride for transposed tiles (float4-aligned, conflict-free reads)

// ---------------- scratch (no allocations allowed) ----------------
__device__ float g_qkv[T_LEN * 3 * DIM];            // [T][3*768]
__device__ float g_Q[HEADS * T_LEN * HD];           // [h][t][d]
__device__ float g_K[HEADS * T_LEN * HD];
__device__ float g_V[HEADS * T_LEN * HD];
__device__ float g_Y[T_LEN * DIM];                  // attention out [t][h*64+d]

// ---------------- GEMM: C[M,N] = A[M,K] * B[N,K]^T (both K-contiguous) ----------------
__global__ __launch_bounds__(256) void gemm_nt(const float* __restrict__ A,
                                               const float* __restrict__ B,
                                               float* __restrict__ C,
                                               int M, int N, int K) {
    __shared__ float As[16][128];
    __shared__ float Bs[16][128];
    const int tid = threadIdx.x;
    const int tx = tid & 15;
    const int ty = tid >> 4;
    const int row0 = blockIdx.y * 128;
    const int col0 = blockIdx.x * 128;

    float acc[8][8];
#pragma unroll
    for (int i = 0; i < 8; i++)
#pragma unroll
        for (int j = 0; j < 8; j++) acc[i][j] = 0.f;

    for (int k0 = 0; k0 < K; k0 += 16) {
#pragma unroll
        for (int i = 0; i < 2; i++) {
            int id = tid + i * 256;
            int r = id >> 2;
            int c = (id & 3) << 2;
            float4 a = *(const float4*)&A[(size_t)(row0 + r) * K + k0 + c];
            As[c + 0][r] = a.x; As[c + 1][r] = a.y;
            As[c + 2][r] = a.z; As[c + 3][r] = a.w;
            float4 b = *(const float4*)&B[(size_t)(col0 + r) * K + k0 + c];
            Bs[c + 0][r] = b.x; Bs[c + 1][r] = b.y;
            Bs[c + 2][r] = b.z; Bs[c + 3][r] = b.w;
        }
        __syncthreads();
#pragma unroll
        for (int k = 0; k < 16; k++) {
            float a[8], b[8];
            *(float4*)&a[0] = *(float4*)&As[k][ty * 8];
            *(float4*)&a[4] = *(float4*)&As[k][ty * 8 + 4];
            *(float4*)&b[0] = *(float4*)&Bs[k][tx * 8];
            *(float4*)&b[4] = *(float4*)&Bs[k][tx * 8 + 4];
#pragma unroll
            for (int i = 0; i < 8; i++)
#pragma unroll
                for (int j = 0; j < 8; j++) acc[i][j] = fmaf(a[i], b[j], acc[i][j]);
        }
        __syncthreads();
    }

#pragma unroll
    for (int i = 0; i < 8; i++) {
        float* cp = &C[(size_t)(row0 + ty * 8 + i) * N + col0 + tx * 8];
        *(float4*)&cp[0] = make_float4(acc[i][0], acc[i][1], acc[i][2], acc[i][3]);
        *(float4*)&cp[4] = make_float4(acc[i][4], acc[i][5], acc[i][6], acc[i][7]);
    }
}

// ---------------- prep: RMS norm + rotary + relayout to [h][t][d] ----------------
__global__ void prep_kernel(const float* __restrict__ qkv,
                            float* __restrict__ Q, float* __restrict__ K,
                            float* __restrict__ V) {
    int gwarp = (blockIdx.x * blockDim.x + threadIdx.x) >> 5;
    int lane = threadIdx.x & 31;
    if (gwarp >= T_LEN * HEADS) return;
    int t = gwarp / HEADS;
    int h = gwarp % HEADS;
    const float* base = qkv + (size_t)t * (3 * DIM) + h * HD;

    float q1 = base[lane],            q2 = base[lane + 32];
    float k1 = base[DIM + lane],      k2 = base[DIM + lane + 32];
    float v1 = base[2 * DIM + lane],  v2 = base[2 * DIM + lane + 32];

    float sq = q1 * q1 + q2 * q2;
    float sk = k1 * k1 + k2 * k2;
#pragma unroll
    for (int o = 16; o > 0; o >>= 1) {
        sq += __shfl_xor_sync(0xffffffffu, sq, o);
        sk += __shfl_xor_sync(0xffffffffu, sk, o);
    }
    float rq = rsqrtf(sq * (1.f / 64.f) + RMS_EPS);
    float rk = rsqrtf(sk * (1.f / 64.f) + RMS_EPS);
    q1 *= rq; q2 *= rq;
    k1 *= rk; k2 *= rk;

    float freq = (lane < 16) ? exp2f((float)lane * (-10.0f / 15.0f)) : 0.0f;
    float theta = (float)t * freq;
    float s, c;
    sincosf(theta, &s, &c);

    float qy1 = q1 * c + q2 * s;
    float qy2 = -q1 * s + q2 * c;
    float ky1 = k1 * c + k2 * s;
    float ky2 = -k1 * s + k2 * c;

    size_t o = ((size_t)h * T_LEN + t) * HD;
    Q[o + lane] = qy1;  Q[o + lane + 32] = qy2;
    K[o + lane] = ky1;  K[o + lane + 32] = ky2;
    V[o + lane] = v1;   V[o + lane + 32] = v2;
}

// ---------------- FlashAttention-2 style, fp32 register-tiled GEMMs ----------------
// block = 256 threads (16x16), BM=64 queries x BN=64 keys per tile, 4x4 fragments.
__global__ __launch_bounds__(256, 2)
void flash_attn2(const float* __restrict__ Q, const float* __restrict__ K,
                 const float* __restrict__ V, float* __restrict__ Y) {
    extern __shared__ float sm[];
    float* Qs = sm;                       // [64][SPAD] transposed: Qs[d][t]
    float* Ks = Qs + 64 * SPAD;           // [64][SPAD] transposed: Ks[d][t]
    float* Ps = Ks + 64 * SPAD;           // [64][SPAD] transposed: Ps[j][q]
    float* Vs = Ps + 64 * SPAD;           // [64][64]   natural:   Vs[j][d]

    const int h = blockIdx.y;
    const int qb = (gridDim.x - 1) - blockIdx.x;   // longest blocks first
    const int q0 = qb * BM;
    const int tid = threadIdx.x;
    const int tx = tid & 15;
    const int ty = tid >> 4;

    const float* Qg = Q + ((size_t)h * T_LEN + q0) * HD;
    const float* Kh = K + (size_t)h * T_LEN * HD;
    const float* Vh = V + (size_t)h * T_LEN * HD;

    // stage Q transposed (once per block)
#pragma unroll
    for (int i = 0; i < 4; i++) {
        int id = tid + i * 256;
        int t = id >> 4;
        int dg = (id & 15) << 2;
        float4 v = *(const float4*)&Qg[t * HD + dg];
        Qs[(dg + 0) * SPAD + t] = v.x;
        Qs[(dg + 1) * SPAD + t] = v.y;
        Qs[(dg + 2) * SPAD + t] = v.z;
        Qs[(dg + 3) * SPAD + t] = v.w;
    }

    float acco[4][4];
    float m_[4], l_[4];
#pragma unroll
    for (int i = 0; i < 4; i++) {
        m_[i] = -1e30f;
        l_[i] = 0.f;
#pragma unroll
        for (int j = 0; j < 4; j++) acco[i][j] = 0.f;
    }

    const int ntiles = qb + 1;
    for (int it = 0; it < ntiles; it++) {
        const int k0 = it * BN;
        __syncthreads();   // previous GEMM2 done with Vs/Ps
        // stage K transposed + V natural
#pragma unroll
        for (int i = 0; i < 4; i++) {
            int id = tid + i * 256;
            int t = id >> 4;
            int dg = (id & 15) << 2;
            float4 kv = *(const float4*)&Kh[(size_t)(k0 + t) * HD + dg];
            Ks[(dg + 0) * SPAD + t] = kv.x;
            Ks[(dg + 1) * SPAD + t] = kv.y;
            Ks[(dg + 2) * SPAD + t] = kv.z;
            Ks[(dg + 3) * SPAD + t] = kv.w;
            *(float4*)&Vs[t * 64 + dg] = *(const float4*)&Vh[(size_t)(k0 + t) * HD + dg];
        }
        __syncthreads();

        // GEMM1: S = Q @ K^T  (k-dim = d)
        float accs[4][4];
#pragma unroll
        for (int i = 0; i < 4; i++)
#pragma unroll
            for (int j = 0; j < 4; j++) accs[i][j] = 0.f;

#pragma unroll 8
        for (int d = 0; d < 64; d++) {
            float4 a = *(float4*)&Qs[d * SPAD + ty * 4];
            float4 b = *(float4*)&Ks[d * SPAD + tx * 4];
            float av[4] = {a.x, a.y, a.z, a.w};
            float bv[4] = {b.x, b.y, b.z, b.w};
#pragma unroll
            for (int i = 0; i < 4; i++)
#pragma unroll
                for (int j = 0; j < 4; j++)
                    accs[i][j] = fmaf(av[i], bv[j], accs[i][j]);
        }

        // scale + causal mask (only diagonal tile needs it)
        const bool need_mask = (k0 + BN > q0);
#pragma unroll
        for (int i = 0; i < 4; i++)
#pragma unroll
            for (int j = 0; j < 4; j++) {
                float s = accs[i][j] * ATTN_SCALE;
                if (need_mask && (k0 + tx * 4 + j > q0 + ty * 4 + i)) s = -1e30f;
                accs[i][j] = s;
            }

        // online softmax (row groups = 16 threads sharing ty)
#pragma unroll
        for (int i = 0; i < 4; i++) {
            float rm = fmaxf(fmaxf(accs[i][0], accs[i][1]), fmaxf(accs[i][2], accs[i][3]));
#pragma unroll
            for (int o = 8; o > 0; o >>= 1)
                rm = fmaxf(rm, __shfl_xor_sync(0xffffffffu, rm, o));
            float newm = fmaxf(m_[i], rm);
            float corr = __expf(m_[i] - newm);
            m_[i] = newm;
            float rs = 0.f;
#pragma unroll
            for (int j = 0; j < 4; j++) {
                float p = __expf(accs[i][j] - newm);
                accs[i][j] = p;
                rs += p;
            }
#pragma unroll
            for (int o = 8; o > 0; o >>= 1)
                rs += __shfl_xor_sync(0xffffffffu, rs, o);
            l_[i] = l_[i] * corr + rs;
#pragma unroll
            for (int j = 0; j < 4; j++) acco[i][j] *= corr;
            // store P transposed: Ps[key j][query q]
#pragma unroll
            for (int j = 0; j < 4; j++)
                Ps[(tx * 4 + j) * SPAD + ty * 4 + i] = accs[i][j];
        }
        __syncthreads();   // Ps complete

        // GEMM2: O += P @ V  (k-dim = j)
#pragma unroll 8
        for (int j = 0; j < 64; j++) {
            float4 a = *(float4*)&Ps[j * SPAD + ty * 4];
            float4 b = *(float4*)&Vs[j * 64 + tx * 4];
            float av[4] = {a.x, a.y, a.z, a.w};
            float bv[4] = {b.x, b.y, b.z, b.w};
#pragma unroll
            for (int i = 0; i < 4; i++)
#pragma unroll
                for (int jd = 0; jd < 4; jd++)
                    acco[i][jd] = fmaf(av[i], bv[jd], acco[i][jd]);
        }
    }

    // epilogue: normalize and write [t][h*64+d]
#pragma unroll
    for (int i = 0; i < 4; i++) {
        float inv = 1.f / l_[i];
        float* yp = Y + (size_t)(q0 + ty * 4 + i) * DIM + h * HD + tx * 4;
        *(float4*)yp = make_float4(acco[i][0] * inv, acco[i][1] * inv,
                                   acco[i][2] * inv, acco[i][3] * inv);
    }
}

// ---------------- launch ----------------
extern "C" void kernel_launch(void* const* d_in, const int* in_sizes, int n_in,
                              void* d_out, int out_size) {
    const float* x = (const float*)d_in[0];
    const float* qkv_w = (const float*)d_in[1];
    const float* c_proj_w = (const float*)d_in[2];
    float* out = (float*)d_out;

    float *qkv, *Qb, *Kb, *Vb, *Yb;
    cudaGetSymbolAddress((void**)&qkv, g_qkv);
    cudaGetSymbolAddress((void**)&Qb, g_Q);
    cudaGetSymbolAddress((void**)&Kb, g_K);
    cudaGetSymbolAddress((void**)&Vb, g_V);
    cudaGetSymbolAddress((void**)&Yb, g_Y);

    // 1) qkv = x @ qkv_w^T
    {
        dim3 grid(2304 / 128, T_LEN / 128);
        gemm_nt<<<grid, 256>>>(x, qkv_w, qkv, T_LEN, 2304, DIM);
    }
    // 2) RMS + rotary + relayout
    {
        int warps = T_LEN * HEADS;
        int threads = 256;
        int blocks = (warps * 32 + threads - 1) / threads;
        prep_kernel<<<blocks, threads>>>(qkv, Qb, Kb, Vb);
    }
    // 3) causal flash attention (FA2, register-tiled)
    {
        const int smem_bytes = (3 * 64 * SPAD + 64 * 64) * sizeof(float);  // 68608
        cudaFuncSetAttribute(flash_attn2, cudaFuncAttributeMaxDynamicSharedMemorySize, smem_bytes);
        dim3 grid(T_LEN / BM, HEADS);
        flash_attn2<<<grid, 256, smem_bytes>>>(Qb, Kb, Vb, Yb);
    }
    // 4) out = Y @ c_proj_w^T
    {
        dim3 grid(DIM / 128, T_LEN / 128);
        gemm_nt<<<grid, 256>>>(Yb, c_proj_w, out, T_LEN, DIM, DIM);
    }
}

// round 4
// speedup vs baseline: 1.4338x; 1.1296x over previous
#include <cuda_runtime.h>
#include <cuda_bf16.h>
#include <math.h>

#define T_LEN 4096
#define DIM 768
#define HEADS 12
#define HD 64
#define RMS_EPS 1.1920928955078125e-07f
#define ATTN_SCALE 0.12f
#define BM 128
#define BN 64
#define QP 132   // Qs row stride (floats)
#define KP 68    // Ks/Vs row stride
#define PP 68    // Ps row stride

// ---------------- scratch ----------------
__device__ float g_qkv[T_LEN * 3 * DIM];          // [T][3*768]
__device__ float g_Qt[HEADS * HD * T_LEN];        // [h][d][t]  (transposed)
__device__ float g_Kt[HEADS * HD * T_LEN];        // [h][d][t]
__device__ float g_V [HEADS * T_LEN * HD];        // [h][t][d]
__device__ float g_Y [T_LEN * DIM];               // [t][h*64+d]

// ---------------- GEMM: C[M,N] = A[M,K] * B[N,K]^T ----------------
__global__ __launch_bounds__(256) void gemm_nt(const float* __restrict__ A,
                                               const float* __restrict__ B,
                                               float* __restrict__ C,
                                               int M, int N, int K) {
    __shared__ float As[16][128];
    __shared__ float Bs[16][128];
    const int tid = threadIdx.x;
    const int tx = tid & 15;
    const int ty = tid >> 4;
    const int row0 = blockIdx.y * 128;
    const int col0 = blockIdx.x * 128;

    float acc[8][8];
#pragma unroll
    for (int i = 0; i < 8; i++)
#pragma unroll
        for (int j = 0; j < 8; j++) acc[i][j] = 0.f;

    for (int k0 = 0; k0 < K; k0 += 16) {
#pragma unroll
        for (int i = 0; i < 2; i++) {
            int id = tid + i * 256;
            int r = id >> 2;
            int c = (id & 3) << 2;
            float4 a = *(const float4*)&A[(size_t)(row0 + r) * K + k0 + c];
            As[c + 0][r] = a.x; As[c + 1][r] = a.y;
            As[c + 2][r] = a.z; As[c + 3][r] = a.w;
            float4 b = *(const float4*)&B[(size_t)(col0 + r) * K + k0 + c];
            Bs[c + 0][r] = b.x; Bs[c + 1][r] = b.y;
            Bs[c + 2][r] = b.z; Bs[c + 3][r] = b.w;
        }
        __syncthreads();
#pragma unroll
        for (int k = 0; k < 16; k++) {
            float a[8], b[8];
            *(float4*)&a[0] = *(float4*)&As[k][ty * 8];
            *(float4*)&a[4] = *(float4*)&As[k][ty * 8 + 4];
            *(float4*)&b[0] = *(float4*)&Bs[k][tx * 8];
            *(float4*)&b[4] = *(float4*)&Bs[k][tx * 8 + 4];
#pragma unroll
            for (int i = 0; i < 8; i++)
#pragma unroll
                for (int j = 0; j < 8; j++) acc[i][j] = fmaf(a[i], b[j], acc[i][j]);
        }
        __syncthreads();
    }

#pragma unroll
    for (int i = 0; i < 8; i++) {
        float* cp = &C[(size_t)(row0 + ty * 8 + i) * N + col0 + tx * 8];
        *(float4*)&cp[0] = make_float4(acc[i][0], acc[i][1], acc[i][2], acc[i][3]);
        *(float4*)&cp[4] = make_float4(acc[i][4], acc[i][5], acc[i][6], acc[i][7]);
    }
}

// ---------------- prep: RMS + rotary; Q,K -> [h][d][t], V -> [h][t][d] ----------------
__global__ void prep_kernel(const float* __restrict__ qkv,
                            float* __restrict__ Qt, float* __restrict__ Kt,
                            float* __restrict__ V) {
    int gwarp = (blockIdx.x * blockDim.x + threadIdx.x) >> 5;
    int lane = threadIdx.x & 31;
    if (gwarp >= T_LEN * HEADS) return;
    int t = gwarp / HEADS;
    int h = gwarp % HEADS;
    const float* base = qkv + (size_t)t * (3 * DIM) + h * HD;

    float q1 = base[lane],            q2 = base[lane + 32];
    float k1 = base[DIM + lane],      k2 = base[DIM + lane + 32];
    float v1 = base[2 * DIM + lane],  v2 = base[2 * DIM + lane + 32];

    float sq = q1 * q1 + q2 * q2;
    float sk = k1 * k1 + k2 * k2;
#pragma unroll
    for (int o = 16; o > 0; o >>= 1) {
        sq += __shfl_xor_sync(0xffffffffu, sq, o);
        sk += __shfl_xor_sync(0xffffffffu, sk, o);
    }
    float rq = rsqrtf(sq * (1.f / 64.f) + RMS_EPS);
    float rk = rsqrtf(sk * (1.f / 64.f) + RMS_EPS);
    q1 *= rq; q2 *= rq;
    k1 *= rk; k2 *= rk;

    float freq = (lane < 16) ? exp2f((float)lane * (-10.0f / 15.0f)) : 0.0f;
    float theta = (float)t * freq;
    float s, c;
    sincosf(theta, &s, &c);

    float qy1 = q1 * c + q2 * s;
    float qy2 = -q1 * s + q2 * c;
    float ky1 = k1 * c + k2 * s;
    float ky2 = -k1 * s + k2 * c;

    size_t hb = (size_t)h * HD * T_LEN;
    Qt[hb + (size_t)lane * T_LEN + t] = qy1;
    Qt[hb + (size_t)(lane + 32) * T_LEN + t] = qy2;
    Kt[hb + (size_t)lane * T_LEN + t] = ky1;
    Kt[hb + (size_t)(lane + 32) * T_LEN + t] = ky2;
    size_t vo = ((size_t)h * T_LEN + t) * HD;
    V[vo + lane] = v1;  V[vo + lane + 32] = v2;
}

// ---------------- FlashAttention-2, conflict-free smem, 128x64 tiles ----------------
// 256 threads (16x16); thread owns 8 q-rows (ty*8) x 4 cols (tx*4).
__global__ __launch_bounds__(256, 2)
void flash_attn2(const float* __restrict__ Qt, const float* __restrict__ Kt,
                 const float* __restrict__ V, float* __restrict__ Y) {
    extern __shared__ float sm[];
    float* Qs = sm;                    // [64][QP]  Q^T: Qs[d][t]
    float* Ks = Qs + 64 * QP;          // [64][KP]  K^T: Ks[d][t]
    float* Vs = Ks + 64 * KP;          // [64][KP]  V:   Vs[j][d]
    float* Ps = Vs + 64 * KP;          // [128][PP] P:   Ps[q][j]

    const int h = blockIdx.y;
    const int qb = (gridDim.x - 1) - blockIdx.x;   // longest first
    const int q0 = qb * BM;
    const int tid = threadIdx.x;
    const int tx = tid & 15;
    const int ty = tid >> 4;

    const float* Qg = Qt + (size_t)h * HD * T_LEN;
    const float* Kg = Kt + (size_t)h * HD * T_LEN;
    const float* Vg = V + (size_t)h * T_LEN * HD;

    // stage Q^T tile [64 d][128 t] — coalesced loads, conflict-free stores
#pragma unroll
    for (int i = 0; i < 8; i++) {
        int id = tid + i * 256;        // 2048 float4 slots
        int d = id >> 5;
        int tg = (id & 31) << 2;
        float4 v = *(const float4*)&Qg[(size_t)d * T_LEN + q0 + tg];
        *(float4*)&Qs[d * QP + tg] = v;
    }

    float acco[8][4];
    float m_[8], l_[8];
#pragma unroll
    for (int i = 0; i < 8; i++) {
        m_[i] = -1e30f; l_[i] = 0.f;
#pragma unroll
        for (int j = 0; j < 4; j++) acco[i][j] = 0.f;
    }

    const int ntiles = 2 * qb + 2;
    for (int it = 0; it < ntiles; it++) {
        const int k0 = it * BN;
        __syncthreads();               // prev GEMM2 done with Ks/Vs/Ps
        // stage K^T [64 d][64 t] and V [64 t][64 d]
#pragma unroll
        for (int i = 0; i < 4; i++) {
            int id = tid + i * 256;    // 1024 float4 slots
            int r = id >> 4;
            int cg = (id & 15) << 2;
            float4 kv = *(const float4*)&Kg[(size_t)r * T_LEN + k0 + cg];
            *(float4*)&Ks[r * KP + cg] = kv;
            float4 vv = *(const float4*)&Vg[(size_t)(k0 + r) * HD + cg];
            *(float4*)&Vs[r * KP + cg] = vv;
        }
        __syncthreads();

        // GEMM1: S = Q @ K^T (k-dim = d)
        float accs[8][4];
#pragma unroll
        for (int i = 0; i < 8; i++)
#pragma unroll
            for (int j = 0; j < 4; j++) accs[i][j] = 0.f;

#pragma unroll 4
        for (int d = 0; d < 64; d++) {
            float a[8], b[4];
            *(float4*)&a[0] = *(float4*)&Qs[d * QP + ty * 8];
            *(float4*)&a[4] = *(float4*)&Qs[d * QP + ty * 8 + 4];
            *(float4*)&b[0] = *(float4*)&Ks[d * KP + tx * 4];
#pragma unroll
            for (int i = 0; i < 8; i++)
#pragma unroll
                for (int j = 0; j < 4; j++)
                    accs[i][j] = fmaf(a[i], b[j], accs[i][j]);
        }

        // scale + causal mask (only near-diagonal tiles)
        const bool need_mask = (k0 + BN > q0);
#pragma unroll
        for (int i = 0; i < 8; i++)
#pragma unroll
            for (int j = 0; j < 4; j++) {
                float s = accs[i][j] * ATTN_SCALE;
                if (need_mask && (k0 + tx * 4 + j > q0 + ty * 8 + i)) s = -1e30f;
                accs[i][j] = s;
            }

        // online softmax per row (16 tx lanes per row group)
#pragma unroll
        for (int i = 0; i < 8; i++) {
            float rm = fmaxf(fmaxf(accs[i][0], accs[i][1]), fmaxf(accs[i][2], accs[i][3]));
#pragma unroll
            for (int o = 8; o > 0; o >>= 1)
                rm = fmaxf(rm, __shfl_xor_sync(0xffffffffu, rm, o, 16));
            float newm = fmaxf(m_[i], rm);
            float corr = __expf(m_[i] - newm);
            m_[i] = newm;
            float rs = 0.f;
#pragma unroll
            for (int j = 0; j < 4; j++) {
                float p = __expf(accs[i][j] - newm);
                accs[i][j] = p;
                rs += p;
            }
#pragma unroll
            for (int o = 8; o > 0; o >>= 1)
                rs += __shfl_xor_sync(0xffffffffu, rs, o, 16);
            l_[i] = l_[i] * corr + rs;
#pragma unroll
            for (int j = 0; j < 4; j++) acco[i][j] *= corr;
            // store P natural: conflict-free float4
            *(float4*)&Ps[(ty * 8 + i) * PP + tx * 4] =
                make_float4(accs[i][0], accs[i][1], accs[i][2], accs[i][3]);
        }
        __syncthreads();   // Ps complete

        // GEMM2: O += P @ V (k-dim = j), j in steps of 4
#pragma unroll 2
        for (int j0 = 0; j0 < 64; j0 += 4) {
            float4 af[8];
#pragma unroll
            for (int i = 0; i < 8; i++)
                af[i] = *(float4*)&Ps[(ty * 8 + i) * PP + j0];
            float4 b0 = *(float4*)&Vs[(j0 + 0) * KP + tx * 4];
            float4 b1 = *(float4*)&Vs[(j0 + 1) * KP + tx * 4];
            float4 b2 = *(float4*)&Vs[(j0 + 2) * KP + tx * 4];
            float4 b3 = *(float4*)&Vs[(j0 + 3) * KP + tx * 4];
#pragma unroll
            for (int i = 0; i < 8; i++) {
                acco[i][0] = fmaf(af[i].x, b0.x, acco[i][0]);
                acco[i][1] = fmaf(af[i].x, b0.y, acco[i][1]);
                acco[i][2] = fmaf(af[i].x, b0.z, acco[i][2]);
                acco[i][3] = fmaf(af[i].x, b0.w, acco[i][3]);
                acco[i][0] = fmaf(af[i].y, b1.x, acco[i][0]);
                acco[i][1] = fmaf(af[i].y, b1.y, acco[i][1]);
                acco[i][2] = fmaf(af[i].y, b1.z, acco[i][2]);
                acco[i][3] = fmaf(af[i].y, b1.w, acco[i][3]);
                acco[i][0] = fmaf(af[i].z, b2.x, acco[i][0]);
                acco[i][1] = fmaf(af[i].z, b2.y, acco[i][1]);
                acco[i][2] = fmaf(af[i].z, b2.z, acco[i][2]);
                acco[i][3] = fmaf(af[i].z, b2.w, acco[i][3]);
                acco[i][0] = fmaf(af[i].w, b3.x, acco[i][0]);
                acco[i][1] = fmaf(af[i].w, b3.y, acco[i][1]);
                acco[i][2] = fmaf(af[i].w, b3.z, acco[i][2]);
                acco[i][3] = fmaf(af[i].w, b3.w, acco[i][3]);
            }
        }
    }

    // epilogue
#pragma unroll
    for (int i = 0; i < 8; i++) {
        float inv = 1.f / l_[i];
        float* yp = Y + (size_t)(q0 + ty * 8 + i) * DIM + h * HD + tx * 4;
        *(float4*)yp = make_float4(acco[i][0] * inv, acco[i][1] * inv,
                                   acco[i][2] * inv, acco[i][3] * inv);
    }
}

// ---------------- launch ----------------
extern "C" void kernel_launch(void* const* d_in, const int* in_sizes, int n_in,
                              void* d_out, int out_size) {
    const float* x = (const float*)d_in[0];
    const float* qkv_w = (const float*)d_in[1];
    const float* c_proj_w = (const float*)d_in[2];
    float* out = (float*)d_out;

    float *qkv, *Qt, *Kt, *Vb, *Yb;
    cudaGetSymbolAddress((void**)&qkv, g_qkv);
    cudaGetSymbolAddress((void**)&Qt, g_Qt);
    cudaGetSymbolAddress((void**)&Kt, g_Kt);
    cudaGetSymbolAddress((void**)&Vb, g_V);
    cudaGetSymbolAddress((void**)&Yb, g_Y);

    // 1) qkv = x @ qkv_w^T
    {
        dim3 grid(2304 / 128, T_LEN / 128);
        gemm_nt<<<grid, 256>>>(x, qkv_w, qkv, T_LEN, 2304, DIM);
    }
    // 2) RMS + rotary + transpose-relayout
    {
        int warps = T_LEN * HEADS;
        int threads = 256;
        int blocks = (warps * 32 + threads - 1) / threads;
        prep_kernel<<<blocks, threads>>>(qkv, Qt, Kt, Vb);
    }
    // 3) flash attention
    {
        const int smem_bytes = (64 * QP + 64 * KP + 64 * KP + 128 * PP) * (int)sizeof(float);
        cudaFuncSetAttribute(flash_attn2, cudaFuncAttributeMaxDynamicSharedMemorySize, smem_bytes);
        dim3 grid(T_LEN / BM, HEADS);
        flash_attn2<<<grid, 256, smem_bytes>>>(Qt, Kt, Vb, Yb);
    }
    // 4) out = Y @ c_proj_w^T
    {
        dim3 grid(DIM / 128, T_LEN / 128);
        gemm_nt<<<grid, 256>>>(Yb, c_proj_w, out, T_LEN, DIM, DIM);
    }
}